// round 11
// baseline (speedup 1.0000x reference)
#include <cuda_runtime.h>
#include <cstdint>

#define N_NODES 12288
#define H_DIM   128
#define E_EDGES 393216
#define NEGVAL  (-1000000000.0f)
#define ROW4    (N_NODES / 4)          // 3072 float4 per row
#define CAP     256                    // bucket capacity (Poisson(32), max~65)

// P-kernel geometry: one exact wave of 256-thread blocks (no smem).
#define P_GRID    1184                 // 148 SMs x 8 blocks
#define P_THREADS 256
#define P_TOTAL   (P_GRID * P_THREADS)   // 303104 threads
#define P_WARPS   (P_GRID * 8)           // 9472 warps

// D-kernel geometry: one exact wave of 512-thread / 48KB-smem blocks.
#define D_GRID    592                  // 148 SMs x 4 blocks
#define D_THREADS 512

// Static scratch. g_cursor zero-init; self-restored by D each launch.
__device__ float g_d1[N_NODES];
__device__ float g_d2[N_NODES];
__device__ int   g_cursor[N_NODES];
__device__ int2  g_bucket[(size_t)N_NODES * CAP];  // (src_col, float_bits(value))

// Grid-barrier state for P. Epoch monotonic across replays -> no reset.
__device__ unsigned          g_count = 0;
__device__ volatile unsigned g_epoch = 0;

__device__ __forceinline__ void p_grid_barrier() {
    __syncthreads();
    if (threadIdx.x == 0) {
        unsigned my = g_epoch;                   // read BEFORE arriving
        __threadfence();                         // release dots writes
        unsigned old = atomicAdd(&g_count, 1);
        if (old == P_GRID - 1) {
            g_count = 0;                         // all arrived: safe
            __threadfence();
            g_epoch = my + 1;                    // release
        } else {
            while (g_epoch == my) __nanosleep(32);
            __threadfence();                     // acquire
        }
    }
    __syncthreads();
}

// ---------------------------------------------------------------------------
// P: dots (warp-stride) -> grid barrier -> place (thread-stride, precomputed
//    values). Edge-array loads are issued BEFORE the barrier so their latency
//    hides under dots + barrier wait. Exactly one wave -> barrier is safe.
// ---------------------------------------------------------------------------
__global__ __launch_bounds__(P_THREADS, 8)
void prep_kernel(const float* __restrict__ h,
                 const float* __restrict__ W,
                 const float* __restrict__ b,
                 const int*   __restrict__ src,
                 const int*   __restrict__ dst,
                 const float* __restrict__ wts) {
    const int tid   = threadIdx.x;
    const int t     = (int)(blockIdx.x * P_THREADS + tid);
    const int lane  = tid & 31;
    const int gwarp = t >> 5;

    // -- pre-issue edge loads (independent of dots) --
    // thread t owns edges {t, t + P_TOTAL} (E/P_TOTAL < 2; second may be OOB)
    const int  e1    = t;
    const int  e2    = t + P_TOTAL;
    const bool have2 = (e2 < E_EDGES);
    int   s1 = src[e1];
    int   d1 = dst[e1];
    float w1 = wts[e1];
    int   s2 = have2 ? src[e2] : 0;
    int   d2 = have2 ? dst[e2] : 0;
    float w2 = have2 ? wts[e2] : 0.0f;
    const float wlin = __ldg(&W[2 * H_DIM]);
    const float bias = __ldg(&b[0]);

    // -- dots: 1 warp/node, warp-stride (9472 warps over 12288 nodes) --
    {
        const float4* w14 = (const float4*)(W);
        const float4* w24 = (const float4*)(W + H_DIM);
        float4 wa = __ldg(&w14[lane]);
        float4 wb = __ldg(&w24[lane]);
        for (int n = gwarp; n < N_NODES; n += P_WARPS) {
            const float4* hr4 = (const float4*)(h + (size_t)n * H_DIM);
            float4 hv = __ldg(&hr4[lane]);
            float sa = fmaf(hv.x, wa.x, fmaf(hv.y, wa.y, fmaf(hv.z, wa.z, hv.w * wa.w)));
            float sb = fmaf(hv.x, wb.x, fmaf(hv.y, wb.y, fmaf(hv.z, wb.z, hv.w * wb.w)));
#pragma unroll
            for (int off = 16; off; off >>= 1) {
                sa += __shfl_down_sync(0xffffffffu, sa, off);
                sb += __shfl_down_sync(0xffffffffu, sb, off);
            }
            if (lane == 0) { g_d1[n] = sa; g_d2[n] = sb; }
        }
    }

    p_grid_barrier();                            // d1/d2 visible everywhere

    // -- place: gathers + atomics only (edge data already in registers) --
    {
        float va = g_d1[d1] + g_d2[s1] + fmaf(w1, wlin, bias);
        int   pa = atomicAdd(&g_cursor[d1], 1);
        if (pa < CAP)
            g_bucket[(size_t)d1 * CAP + pa] = make_int2(s1, __float_as_int(va));
        if (have2) {
            float vb = g_d1[d2] + g_d2[s2] + fmaf(w2, wlin, bias);
            int   pb = atomicAdd(&g_cursor[d2], 1);
            if (pb < CAP)
                g_bucket[(size_t)d2 * CAP + pb] = make_int2(s2, __float_as_int(vb));
        }
    }
}

// ---------------------------------------------------------------------------
// D: fill + merge (R9-proven). PDL: first-row smem NEG prefill runs before
//    cudaGridDependencySynchronize(), overlapping P's tail.
// ---------------------------------------------------------------------------
__global__ __launch_bounds__(D_THREADS, 4)
void fill_merge_kernel(float4* __restrict__ out) {
    __shared__ float row[N_NODES];               // exactly 48 KB
    float4* row4 = (float4*)row;
    const float4 v = make_float4(NEGVAL, NEGVAL, NEGVAL, NEGVAL);
    const int tid = threadIdx.x;

    // Prefill first row's smem while P drains (touches no global state).
#pragma unroll
    for (int i = tid; i < ROW4; i += D_THREADS) row4[i] = v;

    cudaGridDependencySynchronize();             // buckets + cursors ready

    bool first = true;
    for (int r = blockIdx.x; r < N_NODES; r += D_GRID) {
        int c   = g_cursor[r];                   // broadcast; hidden under fill
        int cnt = (c < CAP) ? c : CAP;

        if (!first) {
#pragma unroll
            for (int i = tid; i < ROW4; i += D_THREADS) row4[i] = v;
        }
        first = false;
        __syncthreads();                         // all cursor[r] reads done

        if (tid == 0) g_cursor[r] = 0;           // self-restore for next launch

        const int2* bkt = &g_bucket[(size_t)r * CAP];
        for (int i = tid; i < cnt; i += D_THREADS) {
            int2 ev = bkt[i];
            row[ev.x] = __int_as_float(ev.y);    // dup races benign
        }
        __syncthreads();

        float4* dstp = out + (size_t)r * ROW4;
#pragma unroll
        for (int i = tid; i < ROW4; i += D_THREADS) __stcs(&dstp[i], row4[i]);
        __syncthreads();                         // stores done before smem reuse
    }
}

// ---------------------------------------------------------------------------
// Launch. Input order (metadata): h, sources, dests, weights, W, b
// ---------------------------------------------------------------------------
extern "C" void kernel_launch(void* const* d_in, const int* in_sizes, int n_in,
                              void* d_out, int out_size) {
    const float* h       = (const float*)d_in[0];
    const int*   sources = (const int*)  d_in[1];
    const int*   dests   = (const int*)  d_in[2];
    const float* weights = (const float*)d_in[3];
    const float* W       = (const float*)d_in[4];
    const float* b       = (const float*)d_in[5];
    float*       out     = (float*)d_out;

    cudaLaunchAttribute pdl[1];
    pdl[0].id = cudaLaunchAttributeProgrammaticStreamSerialization;
    pdl[0].val.programmaticStreamSerializationAllowed = 1;

    // P: fused dots + place. Exactly one wave of 1184 blocks.
    {
        cudaLaunchConfig_t cfg = {};
        cfg.gridDim  = dim3(P_GRID);
        cfg.blockDim = dim3(P_THREADS);
        cfg.attrs    = pdl;
        cfg.numAttrs = 1;
        cudaLaunchKernelEx(&cfg, prep_kernel, h, W, b, sources, dests, weights);
    }

    // D: fill + merge (PDL over P). 4 blocks/SM, one wave.
    {
        cudaLaunchConfig_t cfg = {};
        cfg.gridDim  = dim3(D_GRID);
        cfg.blockDim = dim3(D_THREADS);
        cfg.attrs    = pdl;
        cfg.numAttrs = 1;
        cudaLaunchKernelEx(&cfg, fill_merge_kernel, (float4*)out);
    }
}